// round 13
// baseline (speedup 1.0000x reference)
#include <cuda_runtime.h>
#include <cuda_bf16.h>
#include <cuda_fp16.h>
#include <cstdint>

#define N_NODES 100000
#define N_EDGES 1600000
#define FEAT 128
#define SCAN_BLK 1024
#define N_SBLK ((N_NODES + SCAN_BLK - 1) / SCAN_BLK)   // 98

#define G_GEMM ((N_NODES + 127) / 128)                 // 782 gemm tiles total
#define G_HALF 391                                     // tiles per half
#define G_HIST 512                                     // hist blocks in K2
#define G_FILL 1024                                    // fill blocks in K4

// Scratch (static device globals — no allocation).
__device__ __half g_xw[(size_t)N_NODES * FEAT];  // 25.6 MB (fp16 xw)
__device__ float g_dis[N_NODES];
__device__ int   g_degi[N_NODES];
__device__ int   g_base[N_NODES];
__device__ int   g_cur[N_NODES];
__device__ unsigned long long g_sstat[N_SBLK];   // decoupled-lookback status
__device__ int   g_src[N_EDGES];
__device__ int   g_is64;
// W transposed to [n][k] fp16, k-pairs packed in uint32.
__device__ uint32_t g_Wimg[128 * 64];

// ---------------------------------------------------------------------------
__device__ __forceinline__ long long edge_at(const void* p, long long i) {
    if (g_is64) return ((const long long*)p)[i];
    return (long long)((const int*)p)[i];
}

// Fused: blocks [0,391) zero degi + scan status (+detect int64 in block 0);
//        blocks [391,423) transpose W to [n][k] fp16 packed image.
__global__ void init_wprep_kernel(const unsigned int* __restrict__ w,
                                  const float* __restrict__ W) {
    if (blockIdx.x < 391) {
        int i = blockIdx.x * blockDim.x + threadIdx.x;
        if (i < N_NODES) g_degi[i] = 0;
        if (i < N_SBLK) g_sstat[i] = 0ULL;
        if (blockIdx.x == 0 && threadIdx.x == 0) {
            int is64 = 1;
            for (int k = 0; k < 64; k++)
                if (w[2 * k + 1] != 0u) { is64 = 0; break; }
            g_is64 = is64;
        }
    } else {
        int idx = (blockIdx.x - 391) * blockDim.x + threadIdx.x;  // 0..8191
        if (idx >= 8192) return;
        int n  = idx >> 6;
        int kp = idx & 63;
        float v0 = W[(size_t)(2 * kp) * FEAT + n];
        float v1 = W[(size_t)(2 * kp + 1) * FEAT + n];
        __half h0 = __float2half_rn(v0);
        __half h1 = __float2half_rn(v1);
        g_Wimg[n * 64 + kp] = (uint32_t)__half_as_ushort(h0) |
                              ((uint32_t)__half_as_ushort(h1) << 16);
    }
}

// ---------------------------------------------------------------------------
// Single-pass exclusive scan (decoupled lookback); also dis = rsqrt(deg+1).
// ---------------------------------------------------------------------------
__global__ __launch_bounds__(SCAN_BLK) void scan_kernel() {
    __shared__ int sh[SCAN_BLK];
    __shared__ int s_pref;
    const int bid = blockIdx.x;
    const int tid = threadIdx.x;
    int i = bid * SCAN_BLK + tid;
    int v = (i < N_NODES) ? g_degi[i] : 0;
    if (i < N_NODES) g_dis[i] = rsqrtf((float)v + 1.0f);
    sh[tid] = v;
    __syncthreads();
    #pragma unroll
    for (int off = 1; off < SCAN_BLK; off <<= 1) {
        int t = (tid >= off) ? sh[tid - off] : 0;
        __syncthreads();
        sh[tid] += t;
        __syncthreads();
    }
    int incl = sh[tid];
    if (tid == 0) {
        int total = sh[SCAN_BLK - 1];
        if (bid == 0) {
            atomicExch(&g_sstat[0], (2ULL << 32) | (unsigned)total);
            s_pref = 0;
        } else {
            atomicExch(&g_sstat[bid], (1ULL << 32) | (unsigned)total);
            int pref = 0;
            int j = bid - 1;
            while (true) {
                unsigned long long s;
                do { s = atomicAdd(&g_sstat[j], 0ULL); } while ((s >> 32) == 0ULL);
                pref += (int)(unsigned)s;
                if ((s >> 32) == 2ULL) break;
                j--;
            }
            atomicExch(&g_sstat[bid], (2ULL << 32) | (unsigned)(pref + total));
            s_pref = pref;
        }
    }
    __syncthreads();
    if (i >= N_NODES) return;
    int base = s_pref + incl - v;
    g_base[i] = base;
    g_cur[i]  = base;
}

// ---------------------------------------------------------------------------
// GEMM tile worker (fp16 single term, pipelined x loads, ldmatrix fragments,
// warp tile 64x32). Shared by both fused kernels.
// ---------------------------------------------------------------------------
#define XSP 20   // x tile row stride in uint32 (16 pairs + 4 pad); 80B row
#define WSP 68   // W row stride in uint32 (64 pairs + 4 pad); 272B row
#define GEMM_SMEM ((128 * XSP + 128 * WSP) * 4)   // 45056 bytes

__device__ __forceinline__ void mma_f16(float c[4], const uint32_t a[4],
                                        const uint32_t b[2]) {
    asm volatile(
        "mma.sync.aligned.m16n8k16.row.col.f32.f16.f16.f32 "
        "{%0,%1,%2,%3}, {%4,%5,%6,%7}, {%8,%9}, {%0,%1,%2,%3};"
        : "+f"(c[0]), "+f"(c[1]), "+f"(c[2]), "+f"(c[3])
        : "r"(a[0]), "r"(a[1]), "r"(a[2]), "r"(a[3]), "r"(b[0]), "r"(b[1]));
}

__device__ __forceinline__ void ldsm_x4(uint32_t& r0, uint32_t& r1,
                                        uint32_t& r2, uint32_t& r3,
                                        uint32_t addr) {
    asm volatile(
        "ldmatrix.sync.aligned.m8n8.x4.shared.b16 {%0,%1,%2,%3}, [%4];"
        : "=r"(r0), "=r"(r1), "=r"(r2), "=r"(r3) : "r"(addr));
}

__device__ __forceinline__ void gemm_tile(const float* __restrict__ x,
                                          int tile, uint32_t* smem) {
    uint32_t* xs = smem;                       // [128][XSP] fp16 pairs
    uint32_t* ws = xs + 128 * XSP;             // [128][WSP]

    const int tid  = threadIdx.x;
    const int lane = tid & 31;
    const int w    = tid >> 5;
    const int wm   = w & 1;
    const int wn   = w >> 1;
    const int grp  = lane >> 2;
    const int qid  = lane & 3;
    const int row0 = tile * 128;

    // Copy precomputed W image (L2-resident) into padded SMEM.
    {
        int r = tid >> 1;
        int h = tid & 1;
        const uint4* s = (const uint4*)&g_Wimg[r * 64 + h * 32];
        uint4* d = (uint4*)&ws[r * WSP + h * 32];
        #pragma unroll
        for (int i = 0; i < 8; i++) d[i] = s[i];
    }

    // Preload chunk 0 into registers.
    float4 pre[4];
    #pragma unroll
    for (int i = 0; i < 4; i++) {
        int idx = tid + i * 256;
        int r   = idx >> 3;
        int c4  = idx & 7;
        int gr  = row0 + r;
        pre[i] = make_float4(0.f, 0.f, 0.f, 0.f);
        if (gr < N_NODES)
            pre[i] = *(const float4*)(x + (size_t)gr * FEAT + c4 * 4);
    }

    uint32_t xs_base = (uint32_t)__cvta_generic_to_shared(xs);
    uint32_t ws_base = (uint32_t)__cvta_generic_to_shared(ws);
    uint32_t xa[4], wb[2];
    #pragma unroll
    for (int mt = 0; mt < 4; mt++) {
        int row = 64 * wm + 16 * mt + (lane & 15);
        xa[mt] = xs_base + (uint32_t)(row * XSP + (lane >> 4) * 4) * 4u;
    }
    #pragma unroll
    for (int nt2 = 0; nt2 < 2; nt2++) {
        int n = 32 * wn + 16 * nt2 + (lane & 7) + ((lane >> 4) << 3);
        wb[nt2] = ws_base + (uint32_t)(n * WSP + ((lane >> 3) & 1) * 4) * 4u;
    }

    float acc[4][4][4];
    #pragma unroll
    for (int mt = 0; mt < 4; mt++)
        #pragma unroll
        for (int nt = 0; nt < 4; nt++)
            #pragma unroll
            for (int q = 0; q < 4; q++) acc[mt][nt][q] = 0.0f;

    for (int kc = 0; kc < 4; kc++) {            // K chunk = 32
        #pragma unroll
        for (int i = 0; i < 4; i++) {
            int idx = tid + i * 256;
            int r   = idx >> 3;
            int c4  = idx & 7;
            __half2 p0 = __float22half2_rn(make_float2(pre[i].x, pre[i].y));
            __half2 p1 = __float22half2_rn(make_float2(pre[i].z, pre[i].w));
            xs[r * XSP + c4 * 2 + 0] = *reinterpret_cast<uint32_t*>(&p0);
            xs[r * XSP + c4 * 2 + 1] = *reinterpret_cast<uint32_t*>(&p1);
        }
        __syncthreads();

        if (kc < 3) {
            #pragma unroll
            for (int i = 0; i < 4; i++) {
                int idx = tid + i * 256;
                int r   = idx >> 3;
                int c4  = idx & 7;
                int gr  = row0 + r;
                pre[i] = make_float4(0.f, 0.f, 0.f, 0.f);
                if (gr < N_NODES)
                    pre[i] = *(const float4*)(x + (size_t)gr * FEAT +
                                              (kc + 1) * 32 + c4 * 4);
            }
        }

        #pragma unroll
        for (int ks = 0; ks < 2; ks++) {
            uint32_t xoff = (uint32_t)(ks * 8) * 4u;
            uint32_t woff = (uint32_t)(kc * 16 + ks * 8) * 4u;

            uint32_t a[4][4];
            #pragma unroll
            for (int mt = 0; mt < 4; mt++)
                ldsm_x4(a[mt][0], a[mt][1], a[mt][2], a[mt][3], xa[mt] + xoff);

            uint32_t b[4][2];
            #pragma unroll
            for (int nt2 = 0; nt2 < 2; nt2++)
                ldsm_x4(b[2*nt2][0], b[2*nt2][1], b[2*nt2+1][0], b[2*nt2+1][1],
                        wb[nt2] + woff);

            #pragma unroll
            for (int nt = 0; nt < 4; nt++)
                #pragma unroll
                for (int mt = 0; mt < 4; mt++)
                    mma_f16(acc[mt][nt], a[mt], b[nt]);
        }
        __syncthreads();
    }

    // Epilogue: write fp16 xw.
    #pragma unroll
    for (int mt = 0; mt < 4; mt++) {
        int r0 = row0 + 64 * wm + 16 * mt + grp;
        #pragma unroll
        for (int nt = 0; nt < 4; nt++) {
            int cb = 32 * wn + 8 * nt + 2 * qid;
            if (r0 < N_NODES)
                *(__half2*)(g_xw + (size_t)r0 * FEAT + cb) =
                    __floats2half2_rn(acc[mt][nt][0], acc[mt][nt][1]);
            if (r0 + 8 < N_NODES)
                *(__half2*)(g_xw + (size_t)(r0 + 8) * FEAT + cb) =
                    __floats2half2_rn(acc[mt][nt][2], acc[mt][nt][3]);
        }
    }
}

// ---------------------------------------------------------------------------
// K2: gemm tiles [0, G_HALF) fused with degree histogram (independent work).
// ---------------------------------------------------------------------------
__global__ __launch_bounds__(256) void gemm_hist_kernel(
    const float* __restrict__ x, const void* __restrict__ ei)
{
    if (blockIdx.x >= G_HALF) {
        long long start = (long long)(blockIdx.x - G_HALF) * blockDim.x + threadIdx.x;
        for (long long e = start; e < N_EDGES; e += (long long)G_HIST * 256) {
            int c = (int)edge_at(ei, (long long)N_EDGES + e);
            atomicAdd(&g_degi[c], 1);
        }
        return;
    }
    extern __shared__ uint32_t smem[];
    gemm_tile(x, blockIdx.x, smem);
}

// ---------------------------------------------------------------------------
// K4: gemm tiles [G_HALF, G_GEMM) fused with CSR fill (needs scan done).
// ---------------------------------------------------------------------------
__global__ __launch_bounds__(256) void gemm_fill_kernel(
    const float* __restrict__ x, const void* __restrict__ ei)
{
    if (blockIdx.x >= (G_GEMM - G_HALF)) {
        long long start = (long long)(blockIdx.x - (G_GEMM - G_HALF)) * blockDim.x
                          + threadIdx.x;
        for (long long e = start; e < N_EDGES; e += (long long)G_FILL * 256) {
            int r = (int)edge_at(ei, e);
            int c = (int)edge_at(ei, (long long)N_EDGES + e);
            int pos = atomicAdd(&g_cur[c], 1);
            g_src[pos] = r;
        }
        return;
    }
    extern __shared__ uint32_t smem[];
    gemm_tile(x, G_HALF + blockIdx.x, smem);
}

// ---------------------------------------------------------------------------
// Gather: one warp per target node; fp16 row reads (8B/lane), fp32 accum.
// ---------------------------------------------------------------------------
__device__ __forceinline__ float4 load_row4(long long node, int lane) {
    uint2 u = *((const uint2*)(g_xw + (size_t)node * FEAT) + lane);
    __half2 p0 = *reinterpret_cast<__half2*>(&u.x);
    __half2 p1 = *reinterpret_cast<__half2*>(&u.y);
    float2 f0 = __half22float2(p0);
    float2 f1 = __half22float2(p1);
    return make_float4(f0.x, f0.y, f1.x, f1.y);
}

__global__ __launch_bounds__(256) void gather_kernel(
    const float* __restrict__ b, float* __restrict__ out)
{
    int node = blockIdx.x * 8 + (threadIdx.x >> 5);
    if (node >= N_NODES) return;
    int lane = threadIdx.x & 31;

    float dc = g_dis[node];
    float d2 = dc * dc;

    float4 acc = load_row4(node, lane);
    acc.x *= d2; acc.y *= d2; acc.z *= d2; acc.w *= d2;   // self-loop

    int base = g_base[node];
    int deg  = g_degi[node];

    int i = 0;
    for (; i + 1 < deg; i += 2) {
        int r0 = g_src[base + i];
        int r1 = g_src[base + i + 1];
        float n0 = g_dis[r0] * dc;
        float n1 = g_dis[r1] * dc;
        float4 v0 = load_row4(r0, lane);
        float4 v1 = load_row4(r1, lane);
        acc.x = fmaf(v0.x, n0, acc.x); acc.y = fmaf(v0.y, n0, acc.y);
        acc.z = fmaf(v0.z, n0, acc.z); acc.w = fmaf(v0.w, n0, acc.w);
        acc.x = fmaf(v1.x, n1, acc.x); acc.y = fmaf(v1.y, n1, acc.y);
        acc.z = fmaf(v1.z, n1, acc.z); acc.w = fmaf(v1.w, n1, acc.w);
    }
    if (i < deg) {
        int r0 = g_src[base + i];
        float n0 = g_dis[r0] * dc;
        float4 v0 = load_row4(r0, lane);
        acc.x = fmaf(v0.x, n0, acc.x); acc.y = fmaf(v0.y, n0, acc.y);
        acc.z = fmaf(v0.z, n0, acc.z); acc.w = fmaf(v0.w, n0, acc.w);
    }

    float4 bb = ((const float4*)b)[lane];
    acc.x += bb.x; acc.y += bb.y; acc.z += bb.z; acc.w += bb.w;
    ((float4*)(out + (size_t)node * FEAT))[lane] = acc;
}

// ---------------------------------------------------------------------------
extern "C" void kernel_launch(void* const* d_in, const int* in_sizes, int n_in,
                              void* d_out, int out_size)
{
    const float* x  = (const float*)d_in[0];
    const float* W  = (const float*)d_in[1];
    const float* b  = (const float*)d_in[2];
    const void*  ei = d_in[3];
    float* out = (float*)d_out;

    cudaFuncSetAttribute(gemm_hist_kernel,
                         cudaFuncAttributeMaxDynamicSharedMemorySize, GEMM_SMEM);
    cudaFuncSetAttribute(gemm_fill_kernel,
                         cudaFuncAttributeMaxDynamicSharedMemorySize, GEMM_SMEM);

    init_wprep_kernel<<<391 + 32, 256>>>((const unsigned int*)ei, W);
    gemm_hist_kernel<<<G_HALF + G_HIST, 256, GEMM_SMEM>>>(x, ei);
    scan_kernel<<<N_SBLK, SCAN_BLK>>>();
    gemm_fill_kernel<<<(G_GEMM - G_HALF) + G_FILL, 256, GEMM_SMEM>>>(x, ei);
    gather_kernel<<<(N_NODES + 7) / 8, 256>>>(b, out);
}

// round 14
// speedup vs baseline: 1.2845x; 1.2845x over previous
#include <cuda_runtime.h>
#include <cuda_bf16.h>
#include <cuda_fp16.h>
#include <cstdint>

#define N_NODES 100000
#define N_EDGES 1600000
#define FEAT 128
#define SCAN_BLK 1024
#define N_SBLK ((N_NODES + SCAN_BLK - 1) / SCAN_BLK)   // 98

#define G_GEMM ((N_NODES + 127) / 128)                 // 782 gemm tile blocks
#define G_FILL 1266                                    // fill blocks in fused grid

// Scratch (static device globals — no allocation).
__device__ __half g_xw[(size_t)N_NODES * FEAT];  // 25.6 MB (fp16 xw)
__device__ float g_dis[N_NODES];
__device__ int   g_degi[N_NODES];
__device__ int   g_base[N_NODES];
__device__ int   g_cur[N_NODES];
__device__ unsigned long long g_sstat[N_SBLK];   // decoupled-lookback status
__device__ int   g_src[N_EDGES];
__device__ int   g_is64;
// W transposed to [n][k] fp16, k-pairs packed in uint32.
__device__ uint32_t g_Wimg[128 * 64];

// ---------------------------------------------------------------------------
__device__ __forceinline__ long long edge_at(const void* p, long long i) {
    if (g_is64) return ((const long long*)p)[i];
    return (long long)((const int*)p)[i];
}

// Fused: blocks [0,391) zero degi + scan status (+detect int64 in block 0);
//        blocks [391,423) transpose W to [n][k] fp16 packed image.
__global__ void init_wprep_kernel(const unsigned int* __restrict__ w,
                                  const float* __restrict__ W) {
    if (blockIdx.x < 391) {
        int i = blockIdx.x * blockDim.x + threadIdx.x;
        if (i < N_NODES) g_degi[i] = 0;
        if (i < N_SBLK) g_sstat[i] = 0ULL;
        if (blockIdx.x == 0 && threadIdx.x == 0) {
            int is64 = 1;
            for (int k = 0; k < 64; k++)
                if (w[2 * k + 1] != 0u) { is64 = 0; break; }
            g_is64 = is64;
        }
    } else {
        int idx = (blockIdx.x - 391) * blockDim.x + threadIdx.x;  // 0..8191
        if (idx >= 8192) return;
        int n  = idx >> 6;
        int kp = idx & 63;
        float v0 = W[(size_t)(2 * kp) * FEAT + n];
        float v1 = W[(size_t)(2 * kp + 1) * FEAT + n];
        __half h0 = __float2half_rn(v0);
        __half h1 = __float2half_rn(v1);
        g_Wimg[n * 64 + kp] = (uint32_t)__half_as_ushort(h0) |
                              ((uint32_t)__half_as_ushort(h1) << 16);
    }
}

__global__ void hist_kernel(const void* __restrict__ ei) {
    int e = blockIdx.x * blockDim.x + threadIdx.x;
    if (e >= N_EDGES) return;
    int c = (int)edge_at(ei, (long long)N_EDGES + e);
    atomicAdd(&g_degi[c], 1);
}

// ---------------------------------------------------------------------------
// Single-pass exclusive scan (decoupled lookback); also dis = rsqrt(deg+1).
// ---------------------------------------------------------------------------
__global__ __launch_bounds__(SCAN_BLK) void scan_kernel() {
    __shared__ int sh[SCAN_BLK];
    __shared__ int s_pref;
    const int bid = blockIdx.x;
    const int tid = threadIdx.x;
    int i = bid * SCAN_BLK + tid;
    int v = (i < N_NODES) ? g_degi[i] : 0;
    if (i < N_NODES) g_dis[i] = rsqrtf((float)v + 1.0f);
    sh[tid] = v;
    __syncthreads();
    #pragma unroll
    for (int off = 1; off < SCAN_BLK; off <<= 1) {
        int t = (tid >= off) ? sh[tid - off] : 0;
        __syncthreads();
        sh[tid] += t;
        __syncthreads();
    }
    int incl = sh[tid];
    if (tid == 0) {
        int total = sh[SCAN_BLK - 1];
        if (bid == 0) {
            atomicExch(&g_sstat[0], (2ULL << 32) | (unsigned)total);
            s_pref = 0;
        } else {
            atomicExch(&g_sstat[bid], (1ULL << 32) | (unsigned)total);
            int pref = 0;
            int j = bid - 1;
            while (true) {
                unsigned long long s;
                do { s = atomicAdd(&g_sstat[j], 0ULL); } while ((s >> 32) == 0ULL);
                pref += (int)(unsigned)s;
                if ((s >> 32) == 2ULL) break;
                j--;
            }
            atomicExch(&g_sstat[bid], (2ULL << 32) | (unsigned)(pref + total));
            s_pref = pref;
        }
    }
    __syncthreads();
    if (i >= N_NODES) return;
    int base = s_pref + incl - v;
    g_base[i] = base;
    g_cur[i]  = base;
}

// ---------------------------------------------------------------------------
// Fused GEMM + fill. GEMM: pure fp16 single term, software-pipelined x loads,
// ldmatrix fragment loads, warp tile 64x32 (2M x 4N warps).
// ---------------------------------------------------------------------------
#define XSP 20   // x tile row stride in uint32 (16 pairs + 4 pad); 80B row
#define WSP 68   // W row stride in uint32 (64 pairs + 4 pad); 272B row
#define GEMM_SMEM ((128 * XSP + 128 * WSP) * 4)   // 45056 bytes

__device__ __forceinline__ void mma_f16(float c[4], const uint32_t a[4],
                                        const uint32_t b[2]) {
    asm volatile(
        "mma.sync.aligned.m16n8k16.row.col.f32.f16.f16.f32 "
        "{%0,%1,%2,%3}, {%4,%5,%6,%7}, {%8,%9}, {%0,%1,%2,%3};"
        : "+f"(c[0]), "+f"(c[1]), "+f"(c[2]), "+f"(c[3])
        : "r"(a[0]), "r"(a[1]), "r"(a[2]), "r"(a[3]), "r"(b[0]), "r"(b[1]));
}

__device__ __forceinline__ void ldsm_x4(uint32_t& r0, uint32_t& r1,
                                        uint32_t& r2, uint32_t& r3,
                                        uint32_t addr) {
    asm volatile(
        "ldmatrix.sync.aligned.m8n8.x4.shared.b16 {%0,%1,%2,%3}, [%4];"
        : "=r"(r0), "=r"(r1), "=r"(r2), "=r"(r3) : "r"(addr));
}

__global__ __launch_bounds__(256) void gemm_fill_kernel(
    const float* __restrict__ x, const void* __restrict__ ei)
{
    if (blockIdx.x >= G_GEMM) {
        long long start = (long long)(blockIdx.x - G_GEMM) * blockDim.x + threadIdx.x;
        for (long long e = start; e < N_EDGES; e += (long long)G_FILL * 256) {
            int r = (int)edge_at(ei, e);
            int c = (int)edge_at(ei, (long long)N_EDGES + e);
            int pos = atomicAdd(&g_cur[c], 1);
            g_src[pos] = r;
        }
        return;
    }

    extern __shared__ uint32_t smem[];
    uint32_t* xs = smem;                       // [128][XSP] fp16 pairs
    uint32_t* ws = xs + 128 * XSP;             // [128][WSP]

    const int tid  = threadIdx.x;
    const int lane = tid & 31;
    const int w    = tid >> 5;
    const int wm   = w & 1;         // M warp: rows 64*wm
    const int wn   = w >> 1;        // N warp: cols 32*wn
    const int grp  = lane >> 2;
    const int qid  = lane & 3;
    const int row0 = blockIdx.x * 128;

    // Copy precomputed W image (L2-resident) into padded SMEM.
    {
        int r = tid >> 1;
        int h = tid & 1;
        const uint4* s = (const uint4*)&g_Wimg[r * 64 + h * 32];
        uint4* d = (uint4*)&ws[r * WSP + h * 32];
        #pragma unroll
        for (int i = 0; i < 8; i++) d[i] = s[i];
    }

    // Preload chunk 0 into registers.
    float4 pre[4];
    #pragma unroll
    for (int i = 0; i < 4; i++) {
        int idx = tid + i * 256;
        int r   = idx >> 3;
        int c4  = idx & 7;
        int gr  = row0 + r;
        pre[i] = make_float4(0.f, 0.f, 0.f, 0.f);
        if (gr < N_NODES)
            pre[i] = *(const float4*)(x + (size_t)gr * FEAT + c4 * 4);
    }

    uint32_t xs_base = (uint32_t)__cvta_generic_to_shared(xs);
    uint32_t ws_base = (uint32_t)__cvta_generic_to_shared(ws);
    uint32_t xa[4], wb[2];
    #pragma unroll
    for (int mt = 0; mt < 4; mt++) {
        int row = 64 * wm + 16 * mt + (lane & 15);
        xa[mt] = xs_base + (uint32_t)(row * XSP + (lane >> 4) * 4) * 4u;
    }
    #pragma unroll
    for (int nt2 = 0; nt2 < 2; nt2++) {
        int n = 32 * wn + 16 * nt2 + (lane & 7) + ((lane >> 4) << 3);
        wb[nt2] = ws_base + (uint32_t)(n * WSP + ((lane >> 3) & 1) * 4) * 4u;
    }

    float acc[4][4][4];
    #pragma unroll
    for (int mt = 0; mt < 4; mt++)
        #pragma unroll
        for (int nt = 0; nt < 4; nt++)
            #pragma unroll
            for (int q = 0; q < 4; q++) acc[mt][nt][q] = 0.0f;

    for (int kc = 0; kc < 4; kc++) {            // K chunk = 32
        #pragma unroll
        for (int i = 0; i < 4; i++) {
            int idx = tid + i * 256;
            int r   = idx >> 3;
            int c4  = idx & 7;
            __half2 p0 = __float22half2_rn(make_float2(pre[i].x, pre[i].y));
            __half2 p1 = __float22half2_rn(make_float2(pre[i].z, pre[i].w));
            xs[r * XSP + c4 * 2 + 0] = *reinterpret_cast<uint32_t*>(&p0);
            xs[r * XSP + c4 * 2 + 1] = *reinterpret_cast<uint32_t*>(&p1);
        }
        __syncthreads();

        if (kc < 3) {
            #pragma unroll
            for (int i = 0; i < 4; i++) {
                int idx = tid + i * 256;
                int r   = idx >> 3;
                int c4  = idx & 7;
                int gr  = row0 + r;
                pre[i] = make_float4(0.f, 0.f, 0.f, 0.f);
                if (gr < N_NODES)
                    pre[i] = *(const float4*)(x + (size_t)gr * FEAT +
                                              (kc + 1) * 32 + c4 * 4);
            }
        }

        #pragma unroll
        for (int ks = 0; ks < 2; ks++) {
            uint32_t xoff = (uint32_t)(ks * 8) * 4u;
            uint32_t woff = (uint32_t)(kc * 16 + ks * 8) * 4u;

            uint32_t a[4][4];
            #pragma unroll
            for (int mt = 0; mt < 4; mt++)
                ldsm_x4(a[mt][0], a[mt][1], a[mt][2], a[mt][3], xa[mt] + xoff);

            uint32_t b[4][2];
            #pragma unroll
            for (int nt2 = 0; nt2 < 2; nt2++)
                ldsm_x4(b[2*nt2][0], b[2*nt2][1], b[2*nt2+1][0], b[2*nt2+1][1],
                        wb[nt2] + woff);

            #pragma unroll
            for (int nt = 0; nt < 4; nt++)
                #pragma unroll
                for (int mt = 0; mt < 4; mt++)
                    mma_f16(acc[mt][nt], a[mt], b[nt]);
        }
        __syncthreads();
    }

    // Epilogue: write fp16 xw.
    #pragma unroll
    for (int mt = 0; mt < 4; mt++) {
        int r0 = row0 + 64 * wm + 16 * mt + grp;
        #pragma unroll
        for (int nt = 0; nt < 4; nt++) {
            int cb = 32 * wn + 8 * nt + 2 * qid;
            if (r0 < N_NODES)
                *(__half2*)(g_xw + (size_t)r0 * FEAT + cb) =
                    __floats2half2_rn(acc[mt][nt][0], acc[mt][nt][1]);
            if (r0 + 8 < N_NODES)
                *(__half2*)(g_xw + (size_t)(r0 + 8) * FEAT + cb) =
                    __floats2half2_rn(acc[mt][nt][2], acc[mt][nt][3]);
        }
    }
}

// ---------------------------------------------------------------------------
// Gather: one warp per target node; fp16 row reads (8B/lane), fp32 accum.
// 4 edges in flight per iteration for latency hiding.
// ---------------------------------------------------------------------------
__device__ __forceinline__ float4 load_row4(long long node, int lane) {
    uint2 u = *((const uint2*)(g_xw + (size_t)node * FEAT) + lane);
    __half2 p0 = *reinterpret_cast<__half2*>(&u.x);
    __half2 p1 = *reinterpret_cast<__half2*>(&u.y);
    float2 f0 = __half22float2(p0);
    float2 f1 = __half22float2(p1);
    return make_float4(f0.x, f0.y, f1.x, f1.y);
}

__device__ __forceinline__ void fma4(float4& acc, const float4& v, float n) {
    acc.x = fmaf(v.x, n, acc.x); acc.y = fmaf(v.y, n, acc.y);
    acc.z = fmaf(v.z, n, acc.z); acc.w = fmaf(v.w, n, acc.w);
}

__global__ __launch_bounds__(256) void gather_kernel(
    const float* __restrict__ b, float* __restrict__ out)
{
    int node = blockIdx.x * 8 + (threadIdx.x >> 5);
    if (node >= N_NODES) return;
    int lane = threadIdx.x & 31;

    float dc = g_dis[node];
    float d2 = dc * dc;

    float4 acc = load_row4(node, lane);
    acc.x *= d2; acc.y *= d2; acc.z *= d2; acc.w *= d2;   // self-loop

    int base = g_base[node];
    int deg  = g_degi[node];

    int i = 0;
    for (; i + 3 < deg; i += 4) {
        int r0 = g_src[base + i];
        int r1 = g_src[base + i + 1];
        int r2 = g_src[base + i + 2];
        int r3 = g_src[base + i + 3];
        float n0 = g_dis[r0] * dc;
        float n1 = g_dis[r1] * dc;
        float n2 = g_dis[r2] * dc;
        float n3 = g_dis[r3] * dc;
        float4 v0 = load_row4(r0, lane);
        float4 v1 = load_row4(r1, lane);
        float4 v2 = load_row4(r2, lane);
        float4 v3 = load_row4(r3, lane);
        fma4(acc, v0, n0);
        fma4(acc, v1, n1);
        fma4(acc, v2, n2);
        fma4(acc, v3, n3);
    }
    for (; i < deg; i++) {
        int r0 = g_src[base + i];
        float n0 = g_dis[r0] * dc;
        float4 v0 = load_row4(r0, lane);
        fma4(acc, v0, n0);
    }

    float4 bb = ((const float4*)b)[lane];
    acc.x += bb.x; acc.y += bb.y; acc.z += bb.z; acc.w += bb.w;
    ((float4*)(out + (size_t)node * FEAT))[lane] = acc;
}

// ---------------------------------------------------------------------------
extern "C" void kernel_launch(void* const* d_in, const int* in_sizes, int n_in,
                              void* d_out, int out_size)
{
    const float* x  = (const float*)d_in[0];
    const float* W  = (const float*)d_in[1];
    const float* b  = (const float*)d_in[2];
    const void*  ei = d_in[3];
    float* out = (float*)d_out;

    cudaFuncSetAttribute(gemm_fill_kernel,
                         cudaFuncAttributeMaxDynamicSharedMemorySize, GEMM_SMEM);

    init_wprep_kernel<<<391 + 32, 256>>>((const unsigned int*)ei, W);
    hist_kernel<<<(N_EDGES + 255) / 256, 256>>>(ei);
    scan_kernel<<<N_SBLK, SCAN_BLK>>>();
    gemm_fill_kernel<<<G_GEMM + G_FILL, 256, GEMM_SMEM>>>(x, ei);
    gather_kernel<<<(N_NODES + 7) / 8, 256>>>(b, out);
}